// round 11
// baseline (speedup 1.0000x reference)
#include <cuda_runtime.h>

// GSA_69063074119914 — scalar-channel spatial-reduction attention.
// ONE launch, producer/consumer handshake inside the kernel.
// Grid (33,16): per batch, CTA r==32 = producer (conv -> g_kv/g_km, flag),
// CTAs r=0..31 = consumers (512 queries each, 32-node local Hermite table).
// All 528 CTAs are co-resident (<= 148*4), so the spin cannot deadlock.
// Flags are reset by the last consumer of each batch -> every graph replay
// starts from identical state.

#define NB     16
#define NSLICE 32      // consumer slices per batch (4 rows each)
#define HW     16384
#define NT     256     // keys per batch
#define NPL    32      // local table nodes per CTA
#define LOG2E  1.4426950408889634f
#define LN2    0.6931471805599453f

__device__ float2 g_kv[NB][NT];        // (k*log2e, v)
__device__ float2 g_km[NB];            // (k2max, k2min)
__device__ volatile int g_flag[NB];    // producer -> consumers
__device__ int g_ack[NB];              // consumer arrival count

__global__ void __launch_bounds__(256, 4) gsa_kernel(
        const float* __restrict__ x,
        const float* __restrict__ wq, const float* __restrict__ bq,
        const float* __restrict__ wk, const float* __restrict__ bk,
        const float* __restrict__ wv, const float* __restrict__ bv,
        const float* __restrict__ cw, const float* __restrict__ cb,
        float* __restrict__ out)
{
    __shared__ float  s_cw[64];
    __shared__ __align__(16) float2 s_kv[NT];
    __shared__ float4 s_part[7][NPL];
    __shared__ float2 s_tab[NPL];
    __shared__ float  s_r0[8], s_r1[8];

    const int b    = blockIdx.y;
    const int r    = blockIdx.x;
    const int t    = threadIdx.x;
    const int lane = t & 31;
    const int warp = t >> 5;
    const float* xb = x + (size_t)b * HW;

    if (r == NSLICE) {
        // ================= PRODUCER: conv -> g_kv, g_km, flag ==============
        const float wk0 = wk[0], bk0 = bk[0];
        const float wv0 = wv[0], bv0 = bv[0];
        const float cb0 = cb[0];
        if (t < 64) s_cw[t] = cw[t];

        const int rr  = t >> 4;
        const int oct = t & 15;
        const float* cbase = xb + (size_t)rr * 1024 + oct * 8;
        float4 u0 = *(const float4*)(cbase + 0 * 128);
        float4 u1 = *(const float4*)(cbase + 0 * 128 + 4);
        float4 u2 = *(const float4*)(cbase + 1 * 128);
        float4 u3 = *(const float4*)(cbase + 1 * 128 + 4);
        float4 u4 = *(const float4*)(cbase + 2 * 128);
        float4 u5 = *(const float4*)(cbase + 2 * 128 + 4);
        float4 u6 = *(const float4*)(cbase + 3 * 128);
        float4 u7 = *(const float4*)(cbase + 3 * 128 + 4);
        __syncthreads();   // s_cw visible

        float d0, d1, d2, d3;
        {
            const float* w = s_cw;
            d0 =       u0.x * w[0];
            d0 = fmaf(u0.y, w[1], d0); d0 = fmaf(u0.z, w[2], d0);
            d0 = fmaf(u0.w, w[3], d0); d0 = fmaf(u1.x, w[4], d0);
            d0 = fmaf(u1.y, w[5], d0); d0 = fmaf(u1.z, w[6], d0);
            d0 = fmaf(u1.w, w[7], d0);
            w = s_cw + 8;
            d1 =       u2.x * w[0];
            d1 = fmaf(u2.y, w[1], d1); d1 = fmaf(u2.z, w[2], d1);
            d1 = fmaf(u2.w, w[3], d1); d1 = fmaf(u3.x, w[4], d1);
            d1 = fmaf(u3.y, w[5], d1); d1 = fmaf(u3.z, w[6], d1);
            d1 = fmaf(u3.w, w[7], d1);
            w = s_cw + 16;
            d2 =       u4.x * w[0];
            d2 = fmaf(u4.y, w[1], d2); d2 = fmaf(u4.z, w[2], d2);
            d2 = fmaf(u4.w, w[3], d2); d2 = fmaf(u5.x, w[4], d2);
            d2 = fmaf(u5.y, w[5], d2); d2 = fmaf(u5.z, w[6], d2);
            d2 = fmaf(u5.w, w[7], d2);
            w = s_cw + 24;
            d3 =       u6.x * w[0];
            d3 = fmaf(u6.y, w[1], d3); d3 = fmaf(u6.z, w[2], d3);
            d3 = fmaf(u6.w, w[3], d3); d3 = fmaf(u7.x, w[4], d3);
            d3 = fmaf(u7.y, w[5], d3); d3 = fmaf(u7.z, w[6], d3);
            d3 = fmaf(u7.w, w[7], d3);
        }
        u0 = *(const float4*)(cbase + 4 * 128);
        u1 = *(const float4*)(cbase + 4 * 128 + 4);
        u2 = *(const float4*)(cbase + 5 * 128);
        u3 = *(const float4*)(cbase + 5 * 128 + 4);
        u4 = *(const float4*)(cbase + 6 * 128);
        u5 = *(const float4*)(cbase + 6 * 128 + 4);
        u6 = *(const float4*)(cbase + 7 * 128);
        u7 = *(const float4*)(cbase + 7 * 128 + 4);
        {
            const float* w = s_cw + 32;
            d0 = fmaf(u0.x, w[0], d0); d0 = fmaf(u0.y, w[1], d0);
            d0 = fmaf(u0.z, w[2], d0); d0 = fmaf(u0.w, w[3], d0);
            d0 = fmaf(u1.x, w[4], d0); d0 = fmaf(u1.y, w[5], d0);
            d0 = fmaf(u1.z, w[6], d0); d0 = fmaf(u1.w, w[7], d0);
            w = s_cw + 40;
            d1 = fmaf(u2.x, w[0], d1); d1 = fmaf(u2.y, w[1], d1);
            d1 = fmaf(u2.z, w[2], d1); d1 = fmaf(u2.w, w[3], d1);
            d1 = fmaf(u3.x, w[4], d1); d1 = fmaf(u3.y, w[5], d1);
            d1 = fmaf(u3.z, w[6], d1); d1 = fmaf(u3.w, w[7], d1);
            w = s_cw + 48;
            d2 = fmaf(u4.x, w[0], d2); d2 = fmaf(u4.y, w[1], d2);
            d2 = fmaf(u4.z, w[2], d2); d2 = fmaf(u4.w, w[3], d2);
            d2 = fmaf(u5.x, w[4], d2); d2 = fmaf(u5.y, w[5], d2);
            d2 = fmaf(u5.z, w[6], d2); d2 = fmaf(u5.w, w[7], d2);
            w = s_cw + 56;
            d3 = fmaf(u6.x, w[0], d3); d3 = fmaf(u6.y, w[1], d3);
            d3 = fmaf(u6.z, w[2], d3); d3 = fmaf(u6.w, w[3], d3);
            d3 = fmaf(u7.x, w[4], d3); d3 = fmaf(u7.y, w[5], d3);
            d3 = fmaf(u7.z, w[6], d3); d3 = fmaf(u7.w, w[7], d3);
        }
        const float ds = (d0 + d1) + (d2 + d3) + cb0;
        const float k2 = fmaf(wk0, ds, bk0) * LOG2E;
        const float vv = fmaf(wv0, ds, bv0);
        g_kv[b][t] = make_float2(k2, vv);

        float kmn = k2, kmx = k2;
#pragma unroll
        for (int off = 16; off > 0; off >>= 1) {
            kmn = fminf(kmn, __shfl_xor_sync(0xffffffffu, kmn, off));
            kmx = fmaxf(kmx, __shfl_xor_sync(0xffffffffu, kmx, off));
        }
        if (lane == 0) { s_r0[warp] = kmn; s_r1[warp] = kmx; }
        __syncthreads();
        if (t == 0) {
            float rmn = s_r0[0], rmx = s_r1[0];
#pragma unroll
            for (int w = 1; w < 8; ++w) {
                rmn = fminf(rmn, s_r0[w]);
                rmx = fmaxf(rmx, s_r1[w]);
            }
            g_km[b] = make_float2(rmx, rmn);
            __threadfence();            // kv + km visible before flag
            g_flag[b] = 1;
        }
        return;
    }

    // ==================== CONSUMER ====================
    const float wq0 = wq[0], bq0 = bq[0];

    // queries: 2 per thread, coalesced (overlaps producer latency)
    const size_t qoff = (size_t)b * HW + (size_t)r * 512 + (size_t)t * 2;
    const float2 xq = *(const float2*)(x + qoff);
    const float q0 = fmaf(wq0, xq.x, bq0);
    const float q1 = fmaf(wq0, xq.y, bq0);

    // local q-range
    float qmn = fminf(q0, q1), qmx = fmaxf(q0, q1);
#pragma unroll
    for (int off = 16; off > 0; off >>= 1) {
        qmn = fminf(qmn, __shfl_xor_sync(0xffffffffu, qmn, off));
        qmx = fmaxf(qmx, __shfl_xor_sync(0xffffffffu, qmx, off));
    }
    if (lane == 0) { s_r0[warp] = qmn; s_r1[warp] = qmx; }

    // wait for producer (single spinner, others park at the barrier)
    if (t == 0) {
        while (g_flag[b] == 0) { __nanosleep(64); }
    }
    __syncthreads();
    __threadfence();   // acquire: order kv/km reads after flag observation

    s_kv[t] = g_kv[b][t];
    const float2 km = g_km[b];

    float qlo = s_r0[0], qhi = s_r1[0];
#pragma unroll
    for (int w = 1; w < 8; ++w) {
        qlo = fminf(qlo, s_r0[w]);
        qhi = fmaxf(qhi, s_r1[w]);
    }
    const float range = qhi - qlo;
    const float hstep = range * (1.0f / (NPL - 1));
    const float scale = (range > 0.f) ? (NPL - 1) / range : 0.f;
    __syncthreads();   // s_kv populated

    // ===== table: node = lane, part = warp (32 keys, LDS broadcast) =====
    {
        const float qn = fmaf(hstep, (float)lane, qlo);
        const float m2 = fmaxf(qn * km.x, qn * km.y);   // exact max exponent

        float S0a = 0.f, S1a = 0.f, S2a = 0.f, S3a = 0.f;
        float S0b = 0.f, S1b = 0.f, S2b = 0.f, S3b = 0.f;
        const float2* kvh = s_kv + warp * 32;
#pragma unroll
        for (int u = 0; u < 32; u += 2) {
            const float4 kk = *(const float4*)(kvh + u);   // 2 (k,v) pairs
            float e0, e1;
            const float x0 = fmaf(qn, kk.x, -m2);
            const float x1 = fmaf(qn, kk.z, -m2);
            asm("ex2.approx.f32 %0, %1;" : "=f"(e0) : "f"(x0));
            asm("ex2.approx.f32 %0, %1;" : "=f"(e1) : "f"(x1));
            const float ve0 = kk.y * e0;
            const float ve1 = kk.w * e1;
            S0a += e0;              S0b += e1;
            S1a += ve0;             S1b += ve1;
            S2a = fmaf(kk.x, e0,  S2a);  S2b = fmaf(kk.z, e1,  S2b);
            S3a = fmaf(kk.x, ve0, S3a);  S3b = fmaf(kk.z, ve1, S3b);
        }
        const float P0 = S0a + S0b, P1 = S1a + S1b;
        const float P2 = S2a + S2b, P3 = S3a + S3b;
        if (warp) s_part[warp - 1][lane] = make_float4(P0, P1, P2, P3);
        __syncthreads();
        if (warp == 0) {
            float T0 = P0, T1 = P1, T2 = P2, T3 = P3;
#pragma unroll
            for (int w = 0; w < 7; ++w) {
                const float4 p = s_part[w][lane];
                T0 += p.x; T1 += p.y; T2 += p.z; T3 += p.w;
            }
            const float rcp = __frcp_rn(T0);
            const float f   = T1 * rcp;
            const float fp  = LN2 * rcp * fmaf(-f, T2, T3);
            s_tab[lane] = make_float2(f, fp * hstep);     // u-space tangent
        }
    }
    __syncthreads();

    // ack + reset (kv fully consumed by this CTA at this point)
    if (t == 0) {
        const int n = atomicAdd(&g_ack[b], 1);
        if (n == NSLICE - 1) {          // last consumer: reset for next replay
            g_ack[b] = 0;
            g_flag[b] = 0;
        }
    }

    // ===== evaluate the 2 in-register queries =====
    float res[2];
    const float qq[2] = { q0, q1 };
#pragma unroll
    for (int e = 0; e < 2; ++e) {
        float tpos = (qq[e] - qlo) * scale;
        tpos = fminf(fmaxf(tpos, 0.f), (float)(NPL - 1));
        const int i = min((int)tpos, NPL - 2);
        const float u = tpos - (float)i;
        const float2 n0 = s_tab[i];
        const float2 n1 = s_tab[i + 1];
        const float d  = n1.x - n0.x;
        const float c2 = 3.f * d - 2.f * n0.y - n1.y;
        const float c3 = n0.y + n1.y - 2.f * d;
        res[e] = fmaf(u, fmaf(u, fmaf(u, c3, c2), n0.y), n0.x);
    }
    *(float2*)(out + qoff) = make_float2(res[0], res[1]);
}

extern "C" void kernel_launch(void* const* d_in, const int* in_sizes, int n_in,
                              void* d_out, int out_size)
{
    // metadata order: x, wq, bq, wk, bk, wv, bv, conv_w, conv_b
    const float* x  = (const float*)d_in[0];
    const float* wq = (const float*)d_in[1];
    const float* bq = (const float*)d_in[2];
    const float* wk = (const float*)d_in[3];
    const float* bk = (const float*)d_in[4];
    const float* wv = (const float*)d_in[5];
    const float* bv = (const float*)d_in[6];
    const float* cw = (const float*)d_in[7];
    const float* cb = (const float*)d_in[8];
    float* out = (float*)d_out;

    gsa_kernel<<<dim3(NSLICE + 1, NB), 256>>>(x, wq, bq, wk, bk, wv, bv, cw, cb, out);
}

// round 12
// speedup vs baseline: 1.1599x; 1.1599x over previous
#include <cuda_runtime.h>

// GSA_69063074119914 — scalar-channel spatial-reduction attention.
// ONE launch, symmetric all-to-all handshake. Grid (16,16): CTA = (cell-row r,
// batch b), 256 threads, all 256 CTAs co-resident (launch_bounds 256,2).
//
// Each CTA's 1024 queries are exactly x rows [8r,8r+8) = conv cell-row r, so
// its 16 conv cells come from the SAME float4s loaded for the queries (zero
// extra global loads). CTAs exchange (k,v) through g_kv + arrive counter,
// then build a 32-node local softmax table (8 warp-parts x 32 keys) and
// evaluate queries by cubic Hermite with exact derivatives.

#define NB    16
#define NCB   16       // CTAs per batch (= cell rows)
#define HW    16384
#define NT    256      // keys per batch
#define NPL   32       // local table nodes per CTA
#define LOG2E 1.4426950408889634f
#define LN2   0.6931471805599453f

__device__ float2 g_kv[NB][NT];   // (k*log2e, v)
__device__ int g_arrive[NB];      // kv-published count
__device__ int g_done[NB];        // kv-consumed count (for reset)

__global__ void __launch_bounds__(256, 2) gsa_kernel(
        const float* __restrict__ x,
        const float* __restrict__ wq, const float* __restrict__ bq,
        const float* __restrict__ wk, const float* __restrict__ bk,
        const float* __restrict__ wv, const float* __restrict__ bv,
        const float* __restrict__ cw, const float* __restrict__ cb,
        float* __restrict__ out)
{
    __shared__ float  s_cw[64];
    __shared__ float  s_red[256];                 // conv partial dots
    __shared__ __align__(16) float2 s_kv[NT];
    __shared__ float4 s_part[7][NPL];
    __shared__ float2 s_tab[NPL];
    __shared__ float  s_qmn[8], s_qmx[8], s_kmn[8], s_kmx[8];

    const int b    = blockIdx.y;
    const int r    = blockIdx.x;                  // cell row / query-slice
    const int t    = threadIdx.x;
    const int lane = t & 31;
    const int warp = t >> 5;

    const float wq0 = wq[0], bq0 = bq[0];
    const float wk0 = wk[0], bk0 = bk[0];
    const float wv0 = wv[0], bv0 = bv[0];
    const float cb0 = cb[0];
    if (t < 64) s_cw[t] = cw[t];

    // ===== load own 4 queries (1 LDG.128, coalesced over the 8-row slice) ===
    // thread t: row p = t>>5 (slice-local 0..7), cols (t&31)*4 .. +3
    const size_t qoff = (size_t)b * HW + (size_t)r * 1024 + (size_t)t * 4;
    const float4 xq = *(const float4*)(x + qoff);

    const float q0 = fmaf(wq0, xq.x, bq0);
    const float q1 = fmaf(wq0, xq.y, bq0);
    const float q2 = fmaf(wq0, xq.z, bq0);
    const float q3 = fmaf(wq0, xq.w, bq0);

    // local q-range
    float qmn = fminf(fminf(q0, q1), fminf(q2, q3));
    float qmx = fmaxf(fmaxf(q0, q1), fmaxf(q2, q3));
#pragma unroll
    for (int off = 16; off > 0; off >>= 1) {
        qmn = fminf(qmn, __shfl_xor_sync(0xffffffffu, qmn, off));
        qmx = fmaxf(qmx, __shfl_xor_sync(0xffffffffu, qmx, off));
    }
    if (lane == 0) { s_qmn[warp] = qmn; s_qmx[warp] = qmx; }
    __syncthreads();   // s_cw visible

    // ===== conv partial: this thread's 4 x-values vs matching weights =====
    // cell j = (t&31)>>1; within-cell cols [(t&1)*4, +4); patch row p = t>>5
    {
        const int p    = t >> 5;
        const int half = t & 1;
        const float4 w4 = *(const float4*)(s_cw + p * 8 + half * 4);
        float part =       xq.x * w4.x;
        part = fmaf(xq.y, w4.y, part);
        part = fmaf(xq.z, w4.z, part);
        part = fmaf(xq.w, w4.w, part);
        s_red[t] = part;
    }
    __syncthreads();

    // finish 16 cells (threads 0..15), publish to g_kv
    if (t < 16) {
        float ds = cb0;
#pragma unroll
        for (int w = 0; w < 8; ++w)
            ds += s_red[w * 32 + t * 2] + s_red[w * 32 + t * 2 + 1];
        const float k2 = fmaf(wk0, ds, bk0) * LOG2E;
        const float vv = fmaf(wv0, ds, bv0);
        g_kv[b][r * 16 + t] = make_float2(k2, vv);
        __threadfence();                    // publish before arrive
    }
    __syncthreads();

    // ===== symmetric barrier across the batch's 16 CTAs =====
    if (t == 0) {
        atomicAdd(&g_arrive[b], 1);
        while (((volatile int*)g_arrive)[b] < NCB) { __nanosleep(32); }
    }
    __syncthreads();
    __threadfence();   // acquire

    // ===== gather all 256 kv (L2-hot), k-range =====
    const float2 kv = g_kv[b][t];
    s_kv[t] = kv;
    float kmn = kv.x, kmx = kv.x;
#pragma unroll
    for (int off = 16; off > 0; off >>= 1) {
        kmn = fminf(kmn, __shfl_xor_sync(0xffffffffu, kmn, off));
        kmx = fmaxf(kmx, __shfl_xor_sync(0xffffffffu, kmx, off));
    }
    if (lane == 0) { s_kmn[warp] = kmn; s_kmx[warp] = kmx; }
    __syncthreads();

    // all g_kv reads done -> last CTA resets counters (replay-deterministic)
    if (t == 0) {
        const int n = atomicAdd(&g_done[b], 1);
        if (n == NCB - 1) { g_done[b] = 0; g_arrive[b] = 0; }
    }

    // redundant final reductions in registers
    float qlo = s_qmn[0], qhi = s_qmx[0];
    kmn = s_kmn[0]; kmx = s_kmx[0];
#pragma unroll
    for (int w = 1; w < 8; ++w) {
        qlo = fminf(qlo, s_qmn[w]);
        qhi = fmaxf(qhi, s_qmx[w]);
        kmn = fminf(kmn, s_kmn[w]);
        kmx = fmaxf(kmx, s_kmx[w]);
    }
    const float range = qhi - qlo;
    const float hstep = range * (1.0f / (NPL - 1));
    const float scale = (range > 0.f) ? (NPL - 1) / range : 0.f;

    // ===== table: node = lane, part = warp (32 keys, LDS broadcast) =====
    {
        const float qn = fmaf(hstep, (float)lane, qlo);
        const float m2 = fmaxf(qn * kmx, qn * kmn);   // exact max exponent

        float S0a = 0.f, S1a = 0.f, S2a = 0.f, S3a = 0.f;
        float S0b = 0.f, S1b = 0.f, S2b = 0.f, S3b = 0.f;
        const float2* kvh = s_kv + warp * 32;
#pragma unroll
        for (int u = 0; u < 32; u += 2) {
            const float4 kk = *(const float4*)(kvh + u);   // 2 (k,v) pairs
            float e0, e1;
            const float x0 = fmaf(qn, kk.x, -m2);
            const float x1 = fmaf(qn, kk.z, -m2);
            asm("ex2.approx.f32 %0, %1;" : "=f"(e0) : "f"(x0));
            asm("ex2.approx.f32 %0, %1;" : "=f"(e1) : "f"(x1));
            const float ve0 = kk.y * e0;
            const float ve1 = kk.w * e1;
            S0a += e0;              S0b += e1;
            S1a += ve0;             S1b += ve1;
            S2a = fmaf(kk.x, e0,  S2a);  S2b = fmaf(kk.z, e1,  S2b);
            S3a = fmaf(kk.x, ve0, S3a);  S3b = fmaf(kk.z, ve1, S3b);
        }
        const float P0 = S0a + S0b, P1 = S1a + S1b;
        const float P2 = S2a + S2b, P3 = S3a + S3b;
        if (warp) s_part[warp - 1][lane] = make_float4(P0, P1, P2, P3);
        __syncthreads();
        if (warp == 0) {
            float T0 = P0, T1 = P1, T2 = P2, T3 = P3;
#pragma unroll
            for (int w = 0; w < 7; ++w) {
                const float4 p = s_part[w][lane];
                T0 += p.x; T1 += p.y; T2 += p.z; T3 += p.w;
            }
            const float rcp = __frcp_rn(T0);
            const float f   = T1 * rcp;
            const float fp  = LN2 * rcp * fmaf(-f, T2, T3);
            s_tab[lane] = make_float2(f, fp * hstep);     // u-space tangent
        }
    }
    __syncthreads();

    // ===== evaluate the 4 in-register queries =====
    float res[4];
    const float qq[4] = { q0, q1, q2, q3 };
#pragma unroll
    for (int e = 0; e < 4; ++e) {
        float tpos = (qq[e] - qlo) * scale;
        tpos = fminf(fmaxf(tpos, 0.f), (float)(NPL - 1));
        const int i = min((int)tpos, NPL - 2);
        const float u = tpos - (float)i;
        const float2 n0 = s_tab[i];
        const float2 n1 = s_tab[i + 1];
        const float d  = n1.x - n0.x;
        const float c2 = 3.f * d - 2.f * n0.y - n1.y;
        const float c3 = n0.y + n1.y - 2.f * d;
        res[e] = fmaf(u, fmaf(u, fmaf(u, c3, c2), n0.y), n0.x);
    }
    *(float4*)(out + qoff) = make_float4(res[0], res[1], res[2], res[3]);
}

extern "C" void kernel_launch(void* const* d_in, const int* in_sizes, int n_in,
                              void* d_out, int out_size)
{
    // metadata order: x, wq, bq, wk, bk, wv, bv, conv_w, conv_b
    const float* x  = (const float*)d_in[0];
    const float* wq = (const float*)d_in[1];
    const float* bq = (const float*)d_in[2];
    const float* wk = (const float*)d_in[3];
    const float* bk = (const float*)d_in[4];
    const float* wv = (const float*)d_in[5];
    const float* bv = (const float*)d_in[6];
    const float* cw = (const float*)d_in[7];
    const float* cb = (const float*)d_in[8];
    float* out = (float*)d_out;

    gsa_kernel<<<dim3(NCB, NB), 256>>>(x, wq, bq, wk, bk, wv, bv, cw, cb, out);
}

// round 13
// speedup vs baseline: 1.4723x; 1.2694x over previous
#include <cuda_runtime.h>

// GSA_69063074119914 — scalar-channel spatial-reduction attention.
// ONE launch, self-sufficient CTAs (R7 chassis). Grid (16,16): CTA =
// (8-row slice, batch), 256 threads, 2 CTAs/SM.
//   conv:  redundant per CTA, 1 cell/thread, ALL 16 LDG.128 prefetched (MLP 16)
//   table: 32 local nodes x 8 warp-parts x 32 keys (R8's proven config)
//   eval:  exact-derivative cubic Hermite, 4 in-register queries/thread

#define NB     16
#define NSLICE 16
#define HW     16384
#define NT     256     // keys per batch
#define NPL    32      // local table nodes per CTA
#define LOG2E  1.4426950408889634f
#define LN2    0.6931471805599453f

__global__ void __launch_bounds__(256, 2) gsa_kernel(
        const float* __restrict__ x,
        const float* __restrict__ wq, const float* __restrict__ bq,
        const float* __restrict__ wk, const float* __restrict__ bk,
        const float* __restrict__ wv, const float* __restrict__ bv,
        const float* __restrict__ cw, const float* __restrict__ cb,
        float* __restrict__ out)
{
    __shared__ float  s_cw[64];
    __shared__ __align__(16) float2 s_kv[NT];    // (k*log2e, v)
    __shared__ float4 s_part[7][NPL];            // warp partial sums
    __shared__ float2 s_tab[NPL];                // (f, f' * hstep)
    __shared__ float  s_qmn[8], s_qmx[8], s_kmn[8], s_kmx[8];

    const int b    = blockIdx.y;
    const int r    = blockIdx.x;                 // 8-row slice
    const int t    = threadIdx.x;
    const int lane = t & 31;
    const int warp = t >> 5;

    const float wq0 = wq[0], bq0 = bq[0];
    const float wk0 = wk[0], bk0 = bk[0];
    const float wv0 = wv[0], bv0 = bv[0];
    const float cb0 = cb[0];
    if (t < 64) s_cw[t] = cw[t];

    const float* xb = x + (size_t)b * HW;

    // ===== queries: 4 per thread (rows [8r,8r+8), 32 threads/row) =====
    const size_t segoff = (size_t)(8 * r + (t >> 5)) * 128 + (size_t)(t & 31) * 4;
    const float4 xq = *(const float4*)(xb + segoff);
    float qv[4] = { fmaf(wq0, xq.x, bq0), fmaf(wq0, xq.y, bq0),
                    fmaf(wq0, xq.z, bq0), fmaf(wq0, xq.w, bq0) };

    // ===== conv: prefetch ALL 16 LDG.128 for cell (rr, oct) =====
    const int rr  = t >> 4;
    const int oct = t & 15;
    const float* cbase = xb + (size_t)rr * 1024 + oct * 8;
    float4 p0  = *(const float4*)(cbase + 0 * 128);
    float4 p1  = *(const float4*)(cbase + 0 * 128 + 4);
    float4 p2  = *(const float4*)(cbase + 1 * 128);
    float4 p3  = *(const float4*)(cbase + 1 * 128 + 4);
    float4 p4  = *(const float4*)(cbase + 2 * 128);
    float4 p5  = *(const float4*)(cbase + 2 * 128 + 4);
    float4 p6  = *(const float4*)(cbase + 3 * 128);
    float4 p7  = *(const float4*)(cbase + 3 * 128 + 4);
    float4 p8  = *(const float4*)(cbase + 4 * 128);
    float4 p9  = *(const float4*)(cbase + 4 * 128 + 4);
    float4 p10 = *(const float4*)(cbase + 5 * 128);
    float4 p11 = *(const float4*)(cbase + 5 * 128 + 4);
    float4 p12 = *(const float4*)(cbase + 6 * 128);
    float4 p13 = *(const float4*)(cbase + 6 * 128 + 4);
    float4 p14 = *(const float4*)(cbase + 7 * 128);
    float4 p15 = *(const float4*)(cbase + 7 * 128 + 4);

    // local q-range while loads fly
    float qmn = fminf(fminf(qv[0], qv[1]), fminf(qv[2], qv[3]));
    float qmx = fmaxf(fmaxf(qv[0], qv[1]), fmaxf(qv[2], qv[3]));
#pragma unroll
    for (int off = 16; off > 0; off >>= 1) {
        qmn = fminf(qmn, __shfl_xor_sync(0xffffffffu, qmn, off));
        qmx = fmaxf(qmx, __shfl_xor_sync(0xffffffffu, qmx, off));
    }
    if (lane == 0) { s_qmn[warp] = qmn; s_qmx[warp] = qmx; }
    __syncthreads();   // s_cw visible

    // conv FMAs, 4 independent accumulators
    float d0, d1, d2, d3;
    {
        const float* w = s_cw;
        d0 =       p0.x  * w[0];
        d0 = fmaf(p0.y,  w[1],  d0); d0 = fmaf(p0.z,  w[2],  d0);
        d0 = fmaf(p0.w,  w[3],  d0); d0 = fmaf(p1.x,  w[4],  d0);
        d0 = fmaf(p1.y,  w[5],  d0); d0 = fmaf(p1.z,  w[6],  d0);
        d0 = fmaf(p1.w,  w[7],  d0);
        d1 =       p2.x  * w[8];
        d1 = fmaf(p2.y,  w[9],  d1); d1 = fmaf(p2.z,  w[10], d1);
        d1 = fmaf(p2.w,  w[11], d1); d1 = fmaf(p3.x,  w[12], d1);
        d1 = fmaf(p3.y,  w[13], d1); d1 = fmaf(p3.z,  w[14], d1);
        d1 = fmaf(p3.w,  w[15], d1);
        d2 =       p4.x  * w[16];
        d2 = fmaf(p4.y,  w[17], d2); d2 = fmaf(p4.z,  w[18], d2);
        d2 = fmaf(p4.w,  w[19], d2); d2 = fmaf(p5.x,  w[20], d2);
        d2 = fmaf(p5.y,  w[21], d2); d2 = fmaf(p5.z,  w[22], d2);
        d2 = fmaf(p5.w,  w[23], d2);
        d3 =       p6.x  * w[24];
        d3 = fmaf(p6.y,  w[25], d3); d3 = fmaf(p6.z,  w[26], d3);
        d3 = fmaf(p6.w,  w[27], d3); d3 = fmaf(p7.x,  w[28], d3);
        d3 = fmaf(p7.y,  w[29], d3); d3 = fmaf(p7.z,  w[30], d3);
        d3 = fmaf(p7.w,  w[31], d3);

        d0 = fmaf(p8.x,  w[32], d0); d0 = fmaf(p8.y,  w[33], d0);
        d0 = fmaf(p8.z,  w[34], d0); d0 = fmaf(p8.w,  w[35], d0);
        d0 = fmaf(p9.x,  w[36], d0); d0 = fmaf(p9.y,  w[37], d0);
        d0 = fmaf(p9.z,  w[38], d0); d0 = fmaf(p9.w,  w[39], d0);
        d1 = fmaf(p10.x, w[40], d1); d1 = fmaf(p10.y, w[41], d1);
        d1 = fmaf(p10.z, w[42], d1); d1 = fmaf(p10.w, w[43], d1);
        d1 = fmaf(p11.x, w[44], d1); d1 = fmaf(p11.y, w[45], d1);
        d1 = fmaf(p11.z, w[46], d1); d1 = fmaf(p11.w, w[47], d1);
        d2 = fmaf(p12.x, w[48], d2); d2 = fmaf(p12.y, w[49], d2);
        d2 = fmaf(p12.z, w[50], d2); d2 = fmaf(p12.w, w[51], d2);
        d2 = fmaf(p13.x, w[52], d2); d2 = fmaf(p13.y, w[53], d2);
        d2 = fmaf(p13.z, w[54], d2); d2 = fmaf(p13.w, w[55], d2);
        d3 = fmaf(p14.x, w[56], d3); d3 = fmaf(p14.y, w[57], d3);
        d3 = fmaf(p14.z, w[58], d3); d3 = fmaf(p14.w, w[59], d3);
        d3 = fmaf(p15.x, w[60], d3); d3 = fmaf(p15.y, w[61], d3);
        d3 = fmaf(p15.z, w[62], d3); d3 = fmaf(p15.w, w[63], d3);
    }
    const float ds = (d0 + d1) + (d2 + d3) + cb0;
    const float k2 = fmaf(wk0, ds, bk0) * LOG2E;
    const float vv = fmaf(wv0, ds, bv0);
    s_kv[t] = make_float2(k2, vv);

    float kmn = k2, kmx = k2;
#pragma unroll
    for (int off = 16; off > 0; off >>= 1) {
        kmn = fminf(kmn, __shfl_xor_sync(0xffffffffu, kmn, off));
        kmx = fmaxf(kmx, __shfl_xor_sync(0xffffffffu, kmx, off));
    }
    if (lane == 0) { s_kmn[warp] = kmn; s_kmx[warp] = kmx; }
    __syncthreads();

    // ===== redundant final reductions in registers =====
    float qlo = s_qmn[0], qhi = s_qmx[0];
    kmn = s_kmn[0]; kmx = s_kmx[0];
#pragma unroll
    for (int w = 1; w < 8; ++w) {
        qlo = fminf(qlo, s_qmn[w]);
        qhi = fmaxf(qhi, s_qmx[w]);
        kmn = fminf(kmn, s_kmn[w]);
        kmx = fmaxf(kmx, s_kmx[w]);
    }
    const float range = qhi - qlo;
    const float hstep = range * (1.0f / (NPL - 1));
    const float scale = (range > 0.f) ? (NPL - 1) / range : 0.f;

    // ===== table: node = lane, part = warp (32 keys, LDS broadcast) =====
    {
        const float qn = fmaf(hstep, (float)lane, qlo);
        const float m2 = fmaxf(qn * kmx, qn * kmn);   // exact max exponent

        float S0a = 0.f, S1a = 0.f, S2a = 0.f, S3a = 0.f;
        float S0b = 0.f, S1b = 0.f, S2b = 0.f, S3b = 0.f;
        const float2* kvh = s_kv + warp * 32;
#pragma unroll
        for (int u = 0; u < 32; u += 2) {
            const float4 kk = *(const float4*)(kvh + u);   // 2 (k,v) pairs
            float e0, e1;
            const float x0 = fmaf(qn, kk.x, -m2);
            const float x1 = fmaf(qn, kk.z, -m2);
            asm("ex2.approx.f32 %0, %1;" : "=f"(e0) : "f"(x0));
            asm("ex2.approx.f32 %0, %1;" : "=f"(e1) : "f"(x1));
            const float ve0 = kk.y * e0;
            const float ve1 = kk.w * e1;
            S0a += e0;              S0b += e1;
            S1a += ve0;             S1b += ve1;
            S2a = fmaf(kk.x, e0,  S2a);  S2b = fmaf(kk.z, e1,  S2b);
            S3a = fmaf(kk.x, ve0, S3a);  S3b = fmaf(kk.z, ve1, S3b);
        }
        const float P0 = S0a + S0b, P1 = S1a + S1b;
        const float P2 = S2a + S2b, P3 = S3a + S3b;
        if (warp) s_part[warp - 1][lane] = make_float4(P0, P1, P2, P3);
        __syncthreads();
        if (warp == 0) {
            float T0 = P0, T1 = P1, T2 = P2, T3 = P3;
#pragma unroll
            for (int w = 0; w < 7; ++w) {
                const float4 p = s_part[w][lane];
                T0 += p.x; T1 += p.y; T2 += p.z; T3 += p.w;
            }
            const float rcp = __frcp_rn(T0);
            const float f   = T1 * rcp;
            const float fp  = LN2 * rcp * fmaf(-f, T2, T3);
            s_tab[lane] = make_float2(f, fp * hstep);     // u-space tangent
        }
    }
    __syncthreads();

    // ===== evaluate the 4 in-register queries =====
    float res[4];
#pragma unroll
    for (int e = 0; e < 4; ++e) {
        float tpos = (qv[e] - qlo) * scale;
        tpos = fminf(fmaxf(tpos, 0.f), (float)(NPL - 1));
        const int i = min((int)tpos, NPL - 2);
        const float u = tpos - (float)i;
        const float2 n0 = s_tab[i];
        const float2 n1 = s_tab[i + 1];
        const float d  = n1.x - n0.x;
        const float c2 = 3.f * d - 2.f * n0.y - n1.y;
        const float c3 = n0.y + n1.y - 2.f * d;
        res[e] = fmaf(u, fmaf(u, fmaf(u, c3, c2), n0.y), n0.x);
    }
    *(float4*)(out + (size_t)b * HW + segoff) =
        make_float4(res[0], res[1], res[2], res[3]);
}

extern "C" void kernel_launch(void* const* d_in, const int* in_sizes, int n_in,
                              void* d_out, int out_size)
{
    // metadata order: x, wq, bq, wk, bk, wv, bv, conv_w, conv_b
    const float* x  = (const float*)d_in[0];
    const float* wq = (const float*)d_in[1];
    const float* bq = (const float*)d_in[2];
    const float* wk = (const float*)d_in[3];
    const float* bk = (const float*)d_in[4];
    const float* wv = (const float*)d_in[5];
    const float* bv = (const float*)d_in[6];
    const float* cw = (const float*)d_in[7];
    const float* cb = (const float*)d_in[8];
    float* out = (float*)d_out;

    gsa_kernel<<<dim3(NSLICE, NB), 256>>>(x, wq, bq, wk, bk, wv, bv, cw, cb, out);
}